// round 2
// baseline (speedup 1.0000x reference)
#include <cuda_runtime.h>
#include <float.h>
#include <math.h>

// Problem constants (fixed by setup_inputs)
#define NPTS 8192
#define KNN 16
#define GS 64
#define NCELLS (GS * GS)

// ---------------- scratch (static device globals; no dynamic allocation) ----
__device__ float    g_mx[NPTS], g_my[NPTS];      // ch2m coordinates (SoA, for gather)
__device__ unsigned g_bbox[4];                   // order-encoded minx,maxx,miny,maxy
__device__ int      g_counts[NCELLS];            // point counts
__device__ int      g_qcounts[NCELLS];           // query counts
__device__ int      g_start[NCELLS + 1];
__device__ int      g_fill[NCELLS];
__device__ int      g_qfill[NCELLS];
__device__ int      g_cellof[NPTS];
__device__ int      g_qcell[NPTS];
__device__ float2   g_bxy[NPTS];                 // binned point coords
__device__ int      g_bid[NPTS];                 // binned original point ids
__device__ float2   g_qxy[NPTS];                 // cell-sorted query coords
__device__ int      g_qid[NPTS];                 // cell-sorted original query ids
__device__ int      g_knn[NPTS * KNN];           // knn[j][k] = k-th nearest ch2m id
__device__ float    g_partial[32];

// Order-preserving float <-> unsigned encoding (for atomicMin/Max)
__device__ __forceinline__ unsigned encf(float f) {
    unsigned u = __float_as_uint(f);
    return (u & 0x80000000u) ? ~u : (u | 0x80000000u);
}
__device__ __forceinline__ float decf(unsigned u) {
    unsigned v = (u & 0x80000000u) ? (u ^ 0x80000000u) : ~u;
    return __uint_as_float(v);
}

// ---------------- kernels --------------------------------------------------

__global__ void k_init() {
    int t = blockIdx.x * blockDim.x + threadIdx.x;
    if (t < NCELLS) { g_counts[t] = 0; g_qcounts[t] = 0; }
    if (t == 0) {
        g_bbox[0] = 0xFFFFFFFFu;  // min x
        g_bbox[1] = 0u;           // max x
        g_bbox[2] = 0xFFFFFFFFu;  // min y
        g_bbox[3] = 0u;           // max y
    }
}

// ch2m = polynomial(ch2, M1, M2); accumulate bounding box of ch2m.
__global__ void k_poly(const float* __restrict__ ch2,
                       const float* __restrict__ M1,
                       const float* __restrict__ M2) {
    int i = blockIdx.x * blockDim.x + threadIdx.x;
    if (i >= NPTS) return;
    float x1 = ch2[2 * i], x2 = ch2[2 * i + 1];
    float y1 = M1[0] + M1[1] * x2 + M1[2] * x1 + M1[3] * x1 * x2;
    float y2 = M2[0] + M2[1] * x2 + M2[2] * x1 + M2[3] * x1 * x2;
    g_mx[i] = y1;
    g_my[i] = y2;
    unsigned ex = encf(y1), ey = encf(y2);
    atomicMin(&g_bbox[0], ex);
    atomicMax(&g_bbox[1], ex);
    atomicMin(&g_bbox[2], ey);
    atomicMax(&g_bbox[3], ey);
}

// Bin points (i < NPTS) and queries (i >= NPTS) into the same grid.
__global__ void k_bin(const float* __restrict__ ch1) {
    int i = blockIdx.x * blockDim.x + threadIdx.x;
    if (i >= 2 * NPTS) return;
    float minx = decf(g_bbox[0]), maxx = decf(g_bbox[1]);
    float miny = decf(g_bbox[2]), maxy = decf(g_bbox[3]);
    float ivx = (float)GS / fmaxf(maxx - minx, 1e-20f);
    float ivy = (float)GS / fmaxf(maxy - miny, 1e-20f);
    if (i < NPTS) {
        int cx = min(GS - 1, max(0, (int)((g_mx[i] - minx) * ivx)));
        int cy = min(GS - 1, max(0, (int)((g_my[i] - miny) * ivy)));
        int c = cy * GS + cx;
        g_cellof[i] = c;
        atomicAdd(&g_counts[c], 1);
    } else {
        int q = i - NPTS;
        float qx = ch1[2 * q], qy = ch1[2 * q + 1];
        int cx = min(GS - 1, max(0, (int)((qx - minx) * ivx)));
        int cy = min(GS - 1, max(0, (int)((qy - miny) * ivy)));
        int c = cy * GS + cx;
        g_qcell[q] = c;
        atomicAdd(&g_qcounts[c], 1);
    }
}

// Shuffle-based exclusive scan of one 4096-int array (1024 threads x int4).
__device__ __forceinline__ void scan4096(const int* __restrict__ cnt,
                                         int* __restrict__ start,
                                         int* __restrict__ fill,
                                         int* __restrict__ wsum,
                                         bool write_total) {
    int t = threadIdx.x;
    int lane = t & 31, w = t >> 5;
    int4 v = ((const int4*)cnt)[t];
    int s1 = v.x, s2 = s1 + v.y, s3 = s2 + v.z, s4 = s3 + v.w;
    int x = s4;
#pragma unroll
    for (int o = 1; o < 32; o <<= 1) {
        int u = __shfl_up_sync(0xFFFFFFFFu, x, o);
        if (lane >= o) x += u;
    }
    if (lane == 31) wsum[w] = x;
    __syncthreads();
    if (w == 0) {
        int y = wsum[lane];
#pragma unroll
        for (int o = 1; o < 32; o <<= 1) {
            int u = __shfl_up_sync(0xFFFFFFFFu, y, o);
            if (lane >= o) y += u;
        }
        wsum[lane] = y;
    }
    __syncthreads();
    int incl = x + (w > 0 ? wsum[w - 1] : 0);
    int excl = incl - s4;
    int4 so = make_int4(excl, excl + s1, excl + s2, excl + s3);
    ((int4*)start)[t] = so;
    ((int4*)fill)[t] = so;
    if (write_total && t == 1023) start[NCELLS] = incl;
}

__global__ void k_scan() {
    __shared__ int wsum[32];
    scan4096(g_counts, g_start, g_fill, wsum, true);
    __syncthreads();
    // queries: start array unused, reuse g_qfill for both roles
    scan4096(g_qcounts, g_qfill, g_qfill, wsum, false);
}

// Scatter points and queries into cell-sorted order.
__global__ void k_scatter(const float* __restrict__ ch1) {
    int i = blockIdx.x * blockDim.x + threadIdx.x;
    if (i >= 2 * NPTS) return;
    if (i < NPTS) {
        int c = g_cellof[i];
        int p = atomicAdd(&g_fill[c], 1);
        g_bxy[p] = make_float2(g_mx[i], g_my[i]);
        g_bid[p] = i;
    } else {
        int q = i - NPTS;
        int c = g_qcell[q];
        int p = atomicAdd(&g_qfill[c], 1);
        g_qxy[p] = make_float2(ch1[2 * q], ch1[2 * q + 1]);
        g_qid[p] = q;
    }
}

// Scan one cell's candidates, maintain sorted ascending top-16 in registers.
#define SCAN_CELL(CX, CY)                                                     \
    do {                                                                      \
        int c_ = (CY) * GS + (CX);                                            \
        int e_ = g_start[c_ + 1];                                             \
        for (int t_ = g_start[c_]; t_ < e_; ++t_) {                           \
            float2 p_ = g_bxy[t_];                                            \
            float dx_ = qx - p_.x;                                            \
            float dy_ = qy - p_.y;                                            \
            float d_ = __fadd_rn(__fmul_rn(dx_, dx_), __fmul_rn(dy_, dy_));   \
            if (d_ < bd[KNN - 1]) {                                           \
                bd[KNN - 1] = d_;                                             \
                bi[KNN - 1] = g_bid[t_];                                      \
                _Pragma("unroll")                                             \
                for (int s_ = KNN - 1; s_ > 0; --s_) {                        \
                    if (bd[s_] < bd[s_ - 1]) {                                \
                        float td_ = bd[s_]; bd[s_] = bd[s_ - 1]; bd[s_ - 1] = td_; \
                        int ti_ = bi[s_]; bi[s_] = bi[s_ - 1]; bi[s_ - 1] = ti_;   \
                    }                                                         \
                }                                                             \
            }                                                                 \
        }                                                                     \
    } while (0)

// For each (cell-sorted) ch1 point: exact 16-NN via expanding Chebyshev rings.
__global__ void k_query() {
    int j = blockIdx.x * blockDim.x + threadIdx.x;
    if (j >= NPTS) return;
    float2 q = g_qxy[j];
    float qx = q.x, qy = q.y;
    int orig = g_qid[j];

    float minx = decf(g_bbox[0]), maxx = decf(g_bbox[1]);
    float miny = decf(g_bbox[2]), maxy = decf(g_bbox[3]);
    float rxr = fmaxf(maxx - minx, 1e-20f);
    float ryr = fmaxf(maxy - miny, 1e-20f);
    float ivx = (float)GS / rxr, ivy = (float)GS / ryr;
    float hx = rxr / (float)GS, hy = ryr / (float)GS;
    int qcx = min(GS - 1, max(0, (int)((qx - minx) * ivx)));
    int qcy = min(GS - 1, max(0, (int)((qy - miny) * ivy)));

    float bd[KNN];
    int bi[KNN];
#pragma unroll
    for (int s = 0; s < KNN; s++) { bd[s] = FLT_MAX; bi[s] = 0; }

    for (int r = 0; r <= GS; ++r) {
        if (r > 0 && bd[KNN - 1] < FLT_MAX) {
            // Lower bound on distance from q to any cell of Chebyshev ring r.
            float b = FLT_MAX;
            if (qcx - r >= 0) b = fminf(b, qx - (minx + (float)(qcx - r + 1) * hx));
            if (qcx + r < GS) b = fminf(b, (minx + (float)(qcx + r) * hx) - qx);
            if (qcy - r >= 0) b = fminf(b, qy - (miny + (float)(qcy - r + 1) * hy));
            if (qcy + r < GS) b = fminf(b, (miny + (float)(qcy + r) * hy) - qy);
            if (b == FLT_MAX) break;            // ring entirely off-grid -> done
            b = fmaxf(b - 1e-4f, 0.0f);         // slack for binning rounding
            if (b * b > bd[KNN - 1]) break;     // no closer point can exist
        }
        if (r == 0) {
            SCAN_CELL(qcx, qcy);
        } else {
            int x0 = max(0, qcx - r), x1 = min(GS - 1, qcx + r);
            if (qcy - r >= 0) for (int cx = x0; cx <= x1; ++cx) SCAN_CELL(cx, qcy - r);
            if (qcy + r < GS) for (int cx = x0; cx <= x1; ++cx) SCAN_CELL(cx, qcy + r);
            int y0 = max(0, qcy - r + 1), y1 = min(GS - 1, qcy + r - 1);
            if (qcx - r >= 0) for (int cy = y0; cy <= y1; ++cy) SCAN_CELL(qcx - r, cy);
            if (qcx + r < GS) for (int cy = y0; cy <= y1; ++cy) SCAN_CELL(qcx + r, cy);
        }
    }

#pragma unroll
    for (int s = 0; s < KNN; s++) g_knn[orig * KNN + s] = bi[s];
}

// Scrambled gather + KL log-sum. knn[k',n'] uses idx[k'*512 + n'/16][n'%16],
// distance evaluated against ch1[n'].
__global__ void k_gather(const float* __restrict__ ch1) {
    int n = blockIdx.x * blockDim.x + threadIdx.x;
    float contrib = 0.0f;
    if (n < NPTS) {
        float qx = ch1[2 * n], qy = ch1[2 * n + 1];
        int q = n >> 4, col = n & 15;
        const float inv_s4 = 1.0f / 2.25f;  // 1 / sigma2^2, sigma2 = 1.5
        float acc = 0.0f;
#pragma unroll
        for (int k = 0; k < 16; k++) {
            int sel = g_knn[(k * 512 + q) * KNN + col];
            float dx = qx - g_mx[sel];
            float dy = qy - g_my[sel];
            float D = 0.5f * (__fmul_rn(dx, dx) * inv_s4 + __fmul_rn(dy, dy) * inv_s4);
            acc += expf(-D);
        }
        float expD = acc * (1.0f / (float)NPTS);
        contrib = (expD != 0.0f) ? logf(expD) : 0.0f;
    }
    __shared__ float sm[256];
    sm[threadIdx.x] = contrib;
    __syncthreads();
    for (int o = 128; o > 0; o >>= 1) {
        if (threadIdx.x < o) sm[threadIdx.x] += sm[threadIdx.x + o];
        __syncthreads();
    }
    if (threadIdx.x == 0) g_partial[blockIdx.x] = sm[0];
}

__global__ void k_final(float* __restrict__ out) {
    float v = (threadIdx.x < 32) ? g_partial[threadIdx.x] : 0.0f;
    for (int o = 16; o > 0; o >>= 1) v += __shfl_down_sync(0xFFFFFFFFu, v, o);
    if (threadIdx.x == 0) out[0] = -v;
}

// ---------------- launch ----------------------------------------------------

extern "C" void kernel_launch(void* const* d_in, const int* in_sizes, int n_in,
                              void* d_out, int out_size) {
    (void)in_sizes; (void)n_in; (void)out_size;
    const float* ch1 = (const float*)d_in[0];
    const float* ch2 = (const float*)d_in[1];
    const float* M1  = (const float*)d_in[2];
    const float* M2  = (const float*)d_in[3];
    float* out = (float*)d_out;

    k_init<<<16, 256>>>();
    k_poly<<<32, 256>>>(ch2, M1, M2);
    k_bin<<<64, 256>>>(ch1);
    k_scan<<<1, 1024>>>();
    k_scatter<<<64, 256>>>(ch1);
    k_query<<<32, 256>>>();
    k_gather<<<32, 256>>>(ch1);
    k_final<<<1, 32>>>(out);
}

// round 3
// speedup vs baseline: 1.5179x; 1.5179x over previous
#include <cuda_runtime.h>
#include <float.h>
#include <math.h>

// Problem constants (fixed by setup_inputs)
#define NPTS 8192
#define KNN 16
#define GS 64
#define NCELLS (GS * GS)

// ---------------- scratch (static device globals; no dynamic allocation) ----
__device__ float    g_mx[NPTS], g_my[NPTS];      // ch2m coordinates (SoA)
__device__ float    g_bboxf[4];                  // minx, maxx, miny, maxy
__device__ int      g_counts[NCELLS];            // point counts
__device__ int      g_qcounts[NCELLS];           // query counts
__device__ int      g_start[NCELLS + 1];
__device__ int      g_fill[NCELLS];
__device__ int      g_qfill[NCELLS];
__device__ int      g_cellof[NPTS];
__device__ int      g_qcell[NPTS];
__device__ float2   g_bxy[NPTS];                 // binned point coords
__device__ int      g_bid[NPTS];                 // binned original point ids
__device__ float2   g_qxy[NPTS];                 // cell-sorted query coords
__device__ int      g_qid[NPTS];                 // cell-sorted original query ids
__device__ int      g_knn[NPTS * KNN];           // knn[j][k] = k-th nearest ch2m id
__device__ float    g_partial[32];

// ---------------- kernels --------------------------------------------------

// Single block: poly map ch2 -> ch2m, bbox reduction, zero the count arrays.
__global__ void k_prep(const float* __restrict__ ch2,
                       const float* __restrict__ M1,
                       const float* __restrict__ M2) {
    __shared__ float s_mnx[32], s_mxx[32], s_mny[32], s_mxy[32];
    int t = threadIdx.x;
    int lane = t & 31, w = t >> 5;
    float m10 = M1[0], m11 = M1[1], m12 = M1[2], m13 = M1[3];
    float m20 = M2[0], m21 = M2[1], m22 = M2[2], m23 = M2[3];
    float mnx = FLT_MAX, mxx = -FLT_MAX, mny = FLT_MAX, mxy = -FLT_MAX;
    for (int i = t; i < NPTS; i += 1024) {
        float x1 = ch2[2 * i], x2 = ch2[2 * i + 1];
        float y1 = m10 + m11 * x2 + m12 * x1 + m13 * x1 * x2;
        float y2 = m20 + m21 * x2 + m22 * x1 + m23 * x1 * x2;
        g_mx[i] = y1;
        g_my[i] = y2;
        mnx = fminf(mnx, y1); mxx = fmaxf(mxx, y1);
        mny = fminf(mny, y2); mxy = fmaxf(mxy, y2);
    }
    // zero count arrays (1024 threads x int4 = 4096 ints each)
    ((int4*)g_counts)[t]  = make_int4(0, 0, 0, 0);
    ((int4*)g_qcounts)[t] = make_int4(0, 0, 0, 0);
#pragma unroll
    for (int o = 16; o > 0; o >>= 1) {
        mnx = fminf(mnx, __shfl_xor_sync(0xFFFFFFFFu, mnx, o));
        mxx = fmaxf(mxx, __shfl_xor_sync(0xFFFFFFFFu, mxx, o));
        mny = fminf(mny, __shfl_xor_sync(0xFFFFFFFFu, mny, o));
        mxy = fmaxf(mxy, __shfl_xor_sync(0xFFFFFFFFu, mxy, o));
    }
    if (lane == 0) { s_mnx[w] = mnx; s_mxx[w] = mxx; s_mny[w] = mny; s_mxy[w] = mxy; }
    __syncthreads();
    if (w == 0) {
        mnx = s_mnx[lane]; mxx = s_mxx[lane]; mny = s_mny[lane]; mxy = s_mxy[lane];
#pragma unroll
        for (int o = 16; o > 0; o >>= 1) {
            mnx = fminf(mnx, __shfl_xor_sync(0xFFFFFFFFu, mnx, o));
            mxx = fmaxf(mxx, __shfl_xor_sync(0xFFFFFFFFu, mxx, o));
            mny = fminf(mny, __shfl_xor_sync(0xFFFFFFFFu, mny, o));
            mxy = fmaxf(mxy, __shfl_xor_sync(0xFFFFFFFFu, mxy, o));
        }
        if (lane == 0) {
            g_bboxf[0] = mnx; g_bboxf[1] = mxx;
            g_bboxf[2] = mny; g_bboxf[3] = mxy;
        }
    }
}

// Bin points (i < NPTS) and queries (i >= NPTS) into the same grid.
__global__ void k_bin(const float* __restrict__ ch1) {
    int i = blockIdx.x * blockDim.x + threadIdx.x;
    if (i >= 2 * NPTS) return;
    float minx = g_bboxf[0], maxx = g_bboxf[1];
    float miny = g_bboxf[2], maxy = g_bboxf[3];
    float ivx = (float)GS / fmaxf(maxx - minx, 1e-20f);
    float ivy = (float)GS / fmaxf(maxy - miny, 1e-20f);
    if (i < NPTS) {
        int cx = min(GS - 1, max(0, (int)((g_mx[i] - minx) * ivx)));
        int cy = min(GS - 1, max(0, (int)((g_my[i] - miny) * ivy)));
        int c = cy * GS + cx;
        g_cellof[i] = c;
        atomicAdd(&g_counts[c], 1);
    } else {
        int q = i - NPTS;
        float qx = ch1[2 * q], qy = ch1[2 * q + 1];
        int cx = min(GS - 1, max(0, (int)((qx - minx) * ivx)));
        int cy = min(GS - 1, max(0, (int)((qy - miny) * ivy)));
        int c = cy * GS + cx;
        g_qcell[q] = c;
        atomicAdd(&g_qcounts[c], 1);
    }
}

// Shuffle-based exclusive scan of one 4096-int array (1024 threads x int4).
__device__ __forceinline__ void scan4096(const int* __restrict__ cnt,
                                         int* __restrict__ start,
                                         int* __restrict__ fill,
                                         int* __restrict__ wsum,
                                         bool write_total) {
    int t = threadIdx.x;
    int lane = t & 31, w = t >> 5;
    int4 v = ((const int4*)cnt)[t];
    int s1 = v.x, s2 = s1 + v.y, s3 = s2 + v.z, s4 = s3 + v.w;
    int x = s4;
#pragma unroll
    for (int o = 1; o < 32; o <<= 1) {
        int u = __shfl_up_sync(0xFFFFFFFFu, x, o);
        if (lane >= o) x += u;
    }
    if (lane == 31) wsum[w] = x;
    __syncthreads();
    if (w == 0) {
        int y = wsum[lane];
#pragma unroll
        for (int o = 1; o < 32; o <<= 1) {
            int u = __shfl_up_sync(0xFFFFFFFFu, y, o);
            if (lane >= o) y += u;
        }
        wsum[lane] = y;
    }
    __syncthreads();
    int incl = x + (w > 0 ? wsum[w - 1] : 0);
    int excl = incl - s4;
    int4 so = make_int4(excl, excl + s1, excl + s2, excl + s3);
    ((int4*)start)[t] = so;
    ((int4*)fill)[t] = so;
    if (write_total && t == 1023) start[NCELLS] = incl;
}

__global__ void k_scan() {
    __shared__ int wsum[32];
    scan4096(g_counts, g_start, g_fill, wsum, true);
    __syncthreads();
    scan4096(g_qcounts, g_qfill, g_qfill, wsum, false);
}

// Scatter points and queries into cell-sorted order.
__global__ void k_scatter(const float* __restrict__ ch1) {
    int i = blockIdx.x * blockDim.x + threadIdx.x;
    if (i >= 2 * NPTS) return;
    if (i < NPTS) {
        int c = g_cellof[i];
        int p = atomicAdd(&g_fill[c], 1);
        g_bxy[p] = make_float2(g_mx[i], g_my[i]);
        g_bid[p] = i;
    } else {
        int q = i - NPTS;
        int c = g_qcell[q];
        int p = atomicAdd(&g_qfill[c], 1);
        g_qxy[p] = make_float2(ch1[2 * q], ch1[2 * q + 1]);
        g_qid[p] = q;
    }
}

// Map ring-cell index i (0..8r-1) to grid coords for Chebyshev ring r>=1.
__device__ __forceinline__ void ring_cell(int r, int i, int qcx, int qcy,
                                          int& cx, int& cy) {
    int side = 2 * r + 1;
    if (i < side) { cx = qcx - r + i; cy = qcy - r; }
    else if (i < 2 * side) { cx = qcx - r + (i - side); cy = qcy + r; }
    else {
        int j = i - 2 * side;
        cy = qcy - r + 1 + (j >> 1);
        cx = (j & 1) ? qcx + r : qcx - r;
    }
}

// One WARP per query: warp-parallel ring counting -> D2 bound -> lane-parallel
// candidate scan with per-lane sorted top-16 -> exact warp merge (sorted).
__global__ void __launch_bounds__(256) k_query() {
    int warp = blockIdx.x * (blockDim.x >> 5) + (threadIdx.x >> 5);
    if (warp >= NPTS) return;
    int lane = threadIdx.x & 31;

    float2 q = g_qxy[warp];
    float qx = q.x, qy = q.y;
    int orig = g_qid[warp];

    float minx = g_bboxf[0], maxx = g_bboxf[1];
    float miny = g_bboxf[2], maxy = g_bboxf[3];
    float rxr = fmaxf(maxx - minx, 1e-20f);
    float ryr = fmaxf(maxy - miny, 1e-20f);
    float ivx = (float)GS / rxr, ivy = (float)GS / ryr;
    float hx = rxr / (float)GS, hy = ryr / (float)GS;
    int qcx = min(GS - 1, max(0, (int)((qx - minx) * ivx)));
    int qcy = min(GS - 1, max(0, (int)((qy - miny) * ivy)));

    // ---- Phase 1: expand rings on CELL COUNTS until >= KNN points covered.
    int r0 = GS;
    int cum = 0;
    for (int r = 0; r <= GS; ++r) {
        int cnt = 0;
        int ncell = (r == 0) ? 1 : 8 * r;
        for (int i = lane; i < ncell; i += 32) {
            int cx, cy;
            if (r == 0) { cx = qcx; cy = qcy; }
            else ring_cell(r, i, qcx, qcy, cx, cy);
            if (cx >= 0 && cx < GS && cy >= 0 && cy < GS) {
                int c = cy * GS + cx;
                cnt += g_start[c + 1] - g_start[c];
            }
        }
#pragma unroll
        for (int o = 16; o > 0; o >>= 1)
            cnt += __shfl_xor_sync(0xFFFFFFFFu, cnt, o);
        cum += cnt;
        if (cum >= KNN) { r0 = r; break; }
    }

    // ---- Phase 2: upper bound D2 on the 16th-NN distance (far corner of the
    // counted region; unclipped coords only enlarge it -> safe).
    float dxf = fmaxf(qx - (minx + (float)(qcx - r0) * hx),
                      (minx + (float)(qcx + r0 + 1) * hx) - qx) + 1e-4f;
    float dyf = fmaxf(qy - (miny + (float)(qcy - r0) * hy),
                      (miny + (float)(qcy + r0 + 1) * hy) - qy) + 1e-4f;
    float D2 = dxf * dxf + dyf * dyf;

    // ---- Phase 3: scan all rings whose lower bound <= D; per-lane sorted top-16.
    float bd[KNN];
    int bi[KNN];
#pragma unroll
    for (int s = 0; s < KNN; s++) { bd[s] = FLT_MAX; bi[s] = 0; }

    for (int r = 0; r <= GS; ++r) {
        if (r > 0) {
            float b = FLT_MAX;
            if (qcx - r >= 0) b = fminf(b, qx - (minx + (float)(qcx - r + 1) * hx));
            if (qcx + r < GS) b = fminf(b, (minx + (float)(qcx + r) * hx) - qx);
            if (qcy - r >= 0) b = fminf(b, qy - (miny + (float)(qcy - r + 1) * hy));
            if (qcy + r < GS) b = fminf(b, (miny + (float)(qcy + r) * hy) - qy);
            if (b == FLT_MAX) break;         // ring entirely off-grid
            b = fmaxf(b - 1e-4f, 0.0f);
            if (b * b > D2) break;           // nothing closer can exist
        }
        int ncell = (r == 0) ? 1 : 8 * r;
        for (int i = lane; i < ncell; i += 32) {
            int cx, cy;
            if (r == 0) { cx = qcx; cy = qcy; }
            else ring_cell(r, i, qcx, qcy, cx, cy);
            if (cx < 0 || cx >= GS || cy < 0 || cy >= GS) continue;
            // per-cell box pruning against D2
            float cx0 = minx + (float)cx * hx;
            float cy0 = miny + (float)cy * hy;
            float ddx = fmaxf(0.0f, fmaxf(cx0 - qx, qx - (cx0 + hx)));
            float ddy = fmaxf(0.0f, fmaxf(cy0 - qy, qy - (cy0 + hy)));
            ddx = fmaxf(ddx - 1e-4f, 0.0f);
            ddy = fmaxf(ddy - 1e-4f, 0.0f);
            if (ddx * ddx + ddy * ddy > D2) continue;
            int c = cy * GS + cx;
            int e = g_start[c + 1];
            for (int t = g_start[c]; t < e; ++t) {
                float2 p = g_bxy[t];
                float dx = qx - p.x;
                float dy = qy - p.y;
                float d = __fadd_rn(__fmul_rn(dx, dx), __fmul_rn(dy, dy));
                if (d < bd[KNN - 1]) {
                    bd[KNN - 1] = d;
                    bi[KNN - 1] = g_bid[t];
#pragma unroll
                    for (int s = KNN - 1; s > 0; --s) {
                        if (bd[s] < bd[s - 1]) {
                            float td = bd[s]; bd[s] = bd[s - 1]; bd[s - 1] = td;
                            int ti = bi[s]; bi[s] = bi[s - 1]; bi[s - 1] = ti;
                        }
                    }
                }
            }
        }
    }

    // ---- Phase 4: exact global sorted top-16 merge across the warp.
    // Per-lane lists are sorted ascending; 16 rounds of warp-argmin over heads.
    for (int k = 0; k < KNN; k++) {
        float bv = bd[0];
        int bl = lane;
#pragma unroll
        for (int o = 16; o > 0; o >>= 1) {
            float ov = __shfl_xor_sync(0xFFFFFFFFu, bv, o);
            int ol = __shfl_xor_sync(0xFFFFFFFFu, bl, o);
            if (ov < bv || (ov == bv && ol < bl)) { bv = ov; bl = ol; }
        }
        if (lane == bl) {
            g_knn[orig * KNN + k] = bi[0];
#pragma unroll
            for (int s = 0; s < KNN - 1; s++) { bd[s] = bd[s + 1]; bi[s] = bi[s + 1]; }
            bd[KNN - 1] = FLT_MAX;
        }
    }
}

// Scrambled gather + KL log-sum. knn[k',n'] uses idx[k'*512 + n'/16][n'%16],
// distance evaluated against ch1[n'].
__global__ void k_gather(const float* __restrict__ ch1) {
    int n = blockIdx.x * blockDim.x + threadIdx.x;
    float contrib = 0.0f;
    if (n < NPTS) {
        float qx = ch1[2 * n], qy = ch1[2 * n + 1];
        int q = n >> 4, col = n & 15;
        const float inv_s4 = 1.0f / 2.25f;  // 1 / sigma2^2, sigma2 = 1.5
        float acc = 0.0f;
#pragma unroll
        for (int k = 0; k < 16; k++) {
            int sel = g_knn[(k * 512 + q) * KNN + col];
            float dx = qx - g_mx[sel];
            float dy = qy - g_my[sel];
            float D = 0.5f * (__fmul_rn(dx, dx) * inv_s4 + __fmul_rn(dy, dy) * inv_s4);
            acc += expf(-D);
        }
        float expD = acc * (1.0f / (float)NPTS);
        contrib = (expD != 0.0f) ? logf(expD) : 0.0f;
    }
    __shared__ float sm[256];
    sm[threadIdx.x] = contrib;
    __syncthreads();
    for (int o = 128; o > 0; o >>= 1) {
        if (threadIdx.x < o) sm[threadIdx.x] += sm[threadIdx.x + o];
        __syncthreads();
    }
    if (threadIdx.x == 0) g_partial[blockIdx.x] = sm[0];
}

__global__ void k_final(float* __restrict__ out) {
    float v = (threadIdx.x < 32) ? g_partial[threadIdx.x] : 0.0f;
    for (int o = 16; o > 0; o >>= 1) v += __shfl_down_sync(0xFFFFFFFFu, v, o);
    if (threadIdx.x == 0) out[0] = -v;
}

// ---------------- launch ----------------------------------------------------

extern "C" void kernel_launch(void* const* d_in, const int* in_sizes, int n_in,
                              void* d_out, int out_size) {
    (void)in_sizes; (void)n_in; (void)out_size;
    const float* ch1 = (const float*)d_in[0];
    const float* ch2 = (const float*)d_in[1];
    const float* M1  = (const float*)d_in[2];
    const float* M2  = (const float*)d_in[3];
    float* out = (float*)d_out;

    k_prep<<<1, 1024>>>(ch2, M1, M2);
    k_bin<<<64, 256>>>(ch1);
    k_scan<<<1, 1024>>>();
    k_scatter<<<64, 256>>>(ch1);
    k_query<<<1024, 256>>>();
    k_gather<<<32, 256>>>(ch1);
    k_final<<<1, 32>>>(out);
}

// round 4
// speedup vs baseline: 1.5662x; 1.0318x over previous
#include <cuda_runtime.h>
#include <float.h>
#include <math.h>

// Problem constants (fixed by setup_inputs)
#define NPTS 8192
#define KNN 16
#define GS 64
#define NCELLS (GS * GS)

// ---------------- scratch (static device globals; no dynamic allocation) ----
__device__ float    g_mx[NPTS], g_my[NPTS];      // ch2m coordinates (SoA)
__device__ float    g_bboxf[4];                  // minx, maxx, miny, maxy
__device__ int      g_start[NCELLS + 1];         // CSR cell starts (points)
__device__ float2   g_bxy[NPTS];                 // binned point coords
__device__ int      g_bid[NPTS];                 // binned original point ids
__device__ float2   g_qxy[NPTS];                 // cell-sorted query coords
__device__ int      g_qid[NPTS];                 // cell-sorted original query ids
__device__ int      g_knn[NPTS * KNN];           // knn[j][k] = k-th nearest ch2m id
__device__ long long g_accum;                    // fixed-point (2^24) sum of logs
__device__ int      g_done;                      // completed-block counter

#define FIXP 16777216.0   // 2^24

// ---------------- kernel A: fused prep (poly+bbox+bin+scan+scatter) --------

// Shuffle-based exclusive scan of a 4096-int smem array (1024 threads x int4).
// In-place: arr[c] becomes exclusive prefix; optionally writes starts to global.
__device__ __forceinline__ void scan4096_smem(int* __restrict__ arr,
                                              int* __restrict__ wsum,
                                              int* __restrict__ gstart) {
    int t = threadIdx.x;
    int lane = t & 31, w = t >> 5;
    int4 v = ((int4*)arr)[t];
    int s1 = v.x, s2 = s1 + v.y, s3 = s2 + v.z, s4 = s3 + v.w;
    int x = s4;
#pragma unroll
    for (int o = 1; o < 32; o <<= 1) {
        int u = __shfl_up_sync(0xFFFFFFFFu, x, o);
        if (lane >= o) x += u;
    }
    if (lane == 31) wsum[w] = x;
    __syncthreads();
    if (w == 0) {
        int y = wsum[lane];
#pragma unroll
        for (int o = 1; o < 32; o <<= 1) {
            int u = __shfl_up_sync(0xFFFFFFFFu, y, o);
            if (lane >= o) y += u;
        }
        wsum[lane] = y;
    }
    __syncthreads();
    int incl = x + (w > 0 ? wsum[w - 1] : 0);
    int excl = incl - s4;
    int4 so = make_int4(excl, excl + s1, excl + s2, excl + s3);
    ((int4*)arr)[t] = so;
    if (gstart) {
        ((int4*)gstart)[t] = so;
        if (t == 1023) gstart[NCELLS] = incl;
    }
}

__global__ void __launch_bounds__(1024) k_prep(const float* __restrict__ ch1,
                                               const float* __restrict__ ch2,
                                               const float* __restrict__ M1,
                                               const float* __restrict__ M2) {
    __shared__ int   s_cnt[NCELLS];    // point counts -> fill offsets
    __shared__ int   s_qcnt[NCELLS];   // query counts -> fill offsets
    __shared__ int   s_wsum[32];
    __shared__ float s_red[128];
    __shared__ float s_bbox[4];

    int t = threadIdx.x;
    int lane = t & 31, w = t >> 5;

    ((int4*)s_cnt)[t]  = make_int4(0, 0, 0, 0);
    ((int4*)s_qcnt)[t] = make_int4(0, 0, 0, 0);
    if (t == 0) { g_accum = 0; g_done = 0; }

    float m10 = M1[0], m11 = M1[1], m12 = M1[2], m13 = M1[3];
    float m20 = M2[0], m21 = M2[1], m22 = M2[2], m23 = M2[3];

    float px[8], py[8];
    float mnx = FLT_MAX, mxx = -FLT_MAX, mny = FLT_MAX, mxy = -FLT_MAX;
#pragma unroll
    for (int u = 0; u < 8; u++) {
        int i = t + u * 1024;
        float2 c = ((const float2*)ch2)[i];
        float y1 = m10 + m11 * c.y + m12 * c.x + m13 * c.x * c.y;
        float y2 = m20 + m21 * c.y + m22 * c.x + m23 * c.x * c.y;
        px[u] = y1; py[u] = y2;
        g_mx[i] = y1; g_my[i] = y2;
        mnx = fminf(mnx, y1); mxx = fmaxf(mxx, y1);
        mny = fminf(mny, y2); mxy = fmaxf(mxy, y2);
    }
    // block-wide bbox reduction
#pragma unroll
    for (int o = 16; o > 0; o >>= 1) {
        mnx = fminf(mnx, __shfl_xor_sync(0xFFFFFFFFu, mnx, o));
        mxx = fmaxf(mxx, __shfl_xor_sync(0xFFFFFFFFu, mxx, o));
        mny = fminf(mny, __shfl_xor_sync(0xFFFFFFFFu, mny, o));
        mxy = fmaxf(mxy, __shfl_xor_sync(0xFFFFFFFFu, mxy, o));
    }
    if (lane == 0) {
        s_red[w] = mnx; s_red[32 + w] = mxx;
        s_red[64 + w] = mny; s_red[96 + w] = mxy;
    }
    __syncthreads();
    if (w == 0) {
        float a = s_red[lane], b = s_red[32 + lane];
        float c = s_red[64 + lane], d = s_red[96 + lane];
#pragma unroll
        for (int o = 16; o > 0; o >>= 1) {
            a = fminf(a, __shfl_xor_sync(0xFFFFFFFFu, a, o));
            b = fmaxf(b, __shfl_xor_sync(0xFFFFFFFFu, b, o));
            c = fminf(c, __shfl_xor_sync(0xFFFFFFFFu, c, o));
            d = fmaxf(d, __shfl_xor_sync(0xFFFFFFFFu, d, o));
        }
        if (lane == 0) {
            s_bbox[0] = a; s_bbox[1] = b; s_bbox[2] = c; s_bbox[3] = d;
            g_bboxf[0] = a; g_bboxf[1] = b; g_bboxf[2] = c; g_bboxf[3] = d;
        }
    }
    __syncthreads();

    float minx = s_bbox[0], maxx = s_bbox[1];
    float miny = s_bbox[2], maxy = s_bbox[3];
    float ivx = (float)GS / fmaxf(maxx - minx, 1e-20f);
    float ivy = (float)GS / fmaxf(maxy - miny, 1e-20f);

    // bin points (counts into smem)
    int pc[8], qc[8];
    float qx[8], qy[8];
#pragma unroll
    for (int u = 0; u < 8; u++) {
        int cx = min(GS - 1, max(0, (int)((px[u] - minx) * ivx)));
        int cy = min(GS - 1, max(0, (int)((py[u] - miny) * ivy)));
        pc[u] = cy * GS + cx;
        atomicAdd(&s_cnt[pc[u]], 1);
        int i = t + u * 1024;
        float2 q = ((const float2*)ch1)[i];
        qx[u] = q.x; qy[u] = q.y;
        int qcx = min(GS - 1, max(0, (int)((q.x - minx) * ivx)));
        int qcy = min(GS - 1, max(0, (int)((q.y - miny) * ivy)));
        qc[u] = qcy * GS + qcx;
        atomicAdd(&s_qcnt[qc[u]], 1);
    }
    __syncthreads();

    scan4096_smem(s_cnt, s_wsum, g_start);
    __syncthreads();
    scan4096_smem(s_qcnt, s_wsum, 0);
    __syncthreads();

    // scatter (cell-sorted order)
#pragma unroll
    for (int u = 0; u < 8; u++) {
        int i = t + u * 1024;
        int p = atomicAdd(&s_cnt[pc[u]], 1);
        g_bxy[p] = make_float2(px[u], py[u]);
        g_bid[p] = i;
        int pq = atomicAdd(&s_qcnt[qc[u]], 1);
        g_qxy[pq] = make_float2(qx[u], qy[u]);
        g_qid[pq] = i;
    }
}

// ---------------- kernel B: warp-per-query exact 16-NN ----------------------

// Map ring-cell index i (0..8r-1) to grid coords for Chebyshev ring r>=1.
__device__ __forceinline__ void ring_cell(int r, int i, int qcx, int qcy,
                                          int& cx, int& cy) {
    int side = 2 * r + 1;
    if (i < side) { cx = qcx - r + i; cy = qcy - r; }
    else if (i < 2 * side) { cx = qcx - r + (i - side); cy = qcy + r; }
    else {
        int j = i - 2 * side;
        cy = qcy - r + 1 + (j >> 1);
        cx = (j & 1) ? qcx + r : qcx - r;
    }
}

__global__ void __launch_bounds__(256) k_query() {
    int warp = blockIdx.x * (blockDim.x >> 5) + (threadIdx.x >> 5);
    if (warp >= NPTS) return;
    int lane = threadIdx.x & 31;

    float2 q = g_qxy[warp];
    float qx = q.x, qy = q.y;
    int orig = g_qid[warp];

    float minx = g_bboxf[0], maxx = g_bboxf[1];
    float miny = g_bboxf[2], maxy = g_bboxf[3];
    float rxr = fmaxf(maxx - minx, 1e-20f);
    float ryr = fmaxf(maxy - miny, 1e-20f);
    float ivx = (float)GS / rxr, ivy = (float)GS / ryr;
    float hx = rxr / (float)GS, hy = ryr / (float)GS;
    int qcx = min(GS - 1, max(0, (int)((qx - minx) * ivx)));
    int qcy = min(GS - 1, max(0, (int)((qy - miny) * ivy)));

    // ---- Phase 1: expand rings on cell counts until >= KNN points covered.
    int r0 = GS;
    int cum = 0;
    for (int r = 0; r <= GS; ++r) {
        int cnt = 0;
        int ncell = (r == 0) ? 1 : 8 * r;
        for (int i = lane; i < ncell; i += 32) {
            int cx, cy;
            if (r == 0) { cx = qcx; cy = qcy; }
            else ring_cell(r, i, qcx, qcy, cx, cy);
            if (cx >= 0 && cx < GS && cy >= 0 && cy < GS) {
                int c = cy * GS + cx;
                cnt += g_start[c + 1] - g_start[c];
            }
        }
        cum += __reduce_add_sync(0xFFFFFFFFu, cnt);
        if (cum >= KNN) { r0 = r; break; }
    }

    // ---- Phase 2: upper bound D2 on the 16th-NN distance (far corner of the
    // counted region; unclipped coords only enlarge it -> safe).
    float dxf = fmaxf(qx - (minx + (float)(qcx - r0) * hx),
                      (minx + (float)(qcx + r0 + 1) * hx) - qx) + 1e-4f;
    float dyf = fmaxf(qy - (miny + (float)(qcy - r0) * hy),
                      (miny + (float)(qcy + r0 + 1) * hy) - qy) + 1e-4f;
    float D2 = dxf * dxf + dyf * dyf;

    // ---- Phase 3: scan all rings whose lower bound <= D; per-lane sorted top-16.
    float bd[KNN];
    int bi[KNN];
#pragma unroll
    for (int s = 0; s < KNN; s++) { bd[s] = FLT_MAX; bi[s] = 0; }

    for (int r = 0; r <= GS; ++r) {
        if (r > 0) {
            float b = FLT_MAX;
            if (qcx - r >= 0) b = fminf(b, qx - (minx + (float)(qcx - r + 1) * hx));
            if (qcx + r < GS) b = fminf(b, (minx + (float)(qcx + r) * hx) - qx);
            if (qcy - r >= 0) b = fminf(b, qy - (miny + (float)(qcy - r + 1) * hy));
            if (qcy + r < GS) b = fminf(b, (miny + (float)(qcy + r) * hy) - qy);
            if (b == FLT_MAX) break;         // ring entirely off-grid
            b = fmaxf(b - 1e-4f, 0.0f);
            if (b * b > D2) break;           // nothing closer can exist
        }
        int ncell = (r == 0) ? 1 : 8 * r;
        for (int i = lane; i < ncell; i += 32) {
            int cx, cy;
            if (r == 0) { cx = qcx; cy = qcy; }
            else ring_cell(r, i, qcx, qcy, cx, cy);
            if (cx < 0 || cx >= GS || cy < 0 || cy >= GS) continue;
            // per-cell box pruning against D2
            float cx0 = minx + (float)cx * hx;
            float cy0 = miny + (float)cy * hy;
            float ddx = fmaxf(0.0f, fmaxf(cx0 - qx, qx - (cx0 + hx)));
            float ddy = fmaxf(0.0f, fmaxf(cy0 - qy, qy - (cy0 + hy)));
            ddx = fmaxf(ddx - 1e-4f, 0.0f);
            ddy = fmaxf(ddy - 1e-4f, 0.0f);
            if (ddx * ddx + ddy * ddy > D2) continue;
            int c = cy * GS + cx;
            int e = g_start[c + 1];
            for (int tt = g_start[c]; tt < e; ++tt) {
                float2 p = g_bxy[tt];
                float dx = qx - p.x;
                float dy = qy - p.y;
                float d = __fadd_rn(__fmul_rn(dx, dx), __fmul_rn(dy, dy));
                if (d < bd[KNN - 1]) {
                    bd[KNN - 1] = d;
                    bi[KNN - 1] = g_bid[tt];
#pragma unroll
                    for (int s = KNN - 1; s > 0; --s) {
                        if (bd[s] < bd[s - 1]) {
                            float td = bd[s]; bd[s] = bd[s - 1]; bd[s - 1] = td;
                            int ti = bi[s]; bi[s] = bi[s - 1]; bi[s - 1] = ti;
                        }
                    }
                }
            }
        }
    }

    // ---- Phase 4: exact global sorted top-16 merge across the warp.
    // Nonneg float bits are order-isomorphic as uint32 -> REDUX min + ballot.
    for (int k = 0; k < KNN; k++) {
        unsigned du = __float_as_uint(bd[0]);
        unsigned m = __reduce_min_sync(0xFFFFFFFFu, du);
        unsigned ball = __ballot_sync(0xFFFFFFFFu, du == m);
        int bl = __ffs(ball) - 1;
        if (lane == bl) {
            g_knn[orig * KNN + k] = bi[0];
#pragma unroll
            for (int s = 0; s < KNN - 1; s++) { bd[s] = bd[s + 1]; bi[s] = bi[s + 1]; }
            bd[KNN - 1] = FLT_MAX;
        }
    }
}

// ---------------- kernel C: scrambled gather + KL log-sum + final -----------

__global__ void __launch_bounds__(256) k_gather(const float* __restrict__ ch1,
                                                float* __restrict__ out) {
    int n = blockIdx.x * blockDim.x + threadIdx.x;
    float contrib = 0.0f;
    {
        float2 qp = ((const float2*)ch1)[n];
        float qx = qp.x, qy = qp.y;
        int q = n >> 4, col = n & 15;
        const float inv_s4 = 1.0f / 2.25f;  // 1 / sigma2^2, sigma2 = 1.5
        float acc = 0.0f;
#pragma unroll
        for (int k = 0; k < 16; k++) {
            int sel = g_knn[(k * 512 + q) * KNN + col];
            float dx = qx - g_mx[sel];
            float dy = qy - g_my[sel];
            float D = 0.5f * (__fmul_rn(dx, dx) * inv_s4 + __fmul_rn(dy, dy) * inv_s4);
            acc += expf(-D);
        }
        float expD = acc * (1.0f / (float)NPTS);
        contrib = (expD != 0.0f) ? logf(expD) : 0.0f;
    }
    __shared__ float sm[256];
    sm[threadIdx.x] = contrib;
    __syncthreads();
    for (int o = 128; o > 0; o >>= 1) {
        if (threadIdx.x < o) sm[threadIdx.x] += sm[threadIdx.x + o];
        __syncthreads();
    }
    if (threadIdx.x == 0) {
        long long v = __double2ll_rn((double)sm[0] * FIXP);
        atomicAdd((unsigned long long*)&g_accum, (unsigned long long)v);
        __threadfence();
        int old = atomicAdd(&g_done, 1);
        if (old == (int)gridDim.x - 1) {
            long long tot = (long long)atomicAdd((unsigned long long*)&g_accum, 0ull);
            out[0] = (float)(-((double)tot / FIXP));
        }
    }
}

// ---------------- launch ----------------------------------------------------

extern "C" void kernel_launch(void* const* d_in, const int* in_sizes, int n_in,
                              void* d_out, int out_size) {
    (void)in_sizes; (void)n_in; (void)out_size;
    const float* ch1 = (const float*)d_in[0];
    const float* ch2 = (const float*)d_in[1];
    const float* M1  = (const float*)d_in[2];
    const float* M2  = (const float*)d_in[3];
    float* out = (float*)d_out;

    k_prep<<<1, 1024>>>(ch1, ch2, M1, M2);
    k_query<<<1024, 256>>>();
    k_gather<<<32, 256>>>(ch1, out);
}